// round 10
// baseline (speedup 1.0000x reference)
#include <cuda_runtime.h>

// 16k -> 24k polyphase resampler (torchaudio/kaldi defaults).
// in_unit=2, out_unit=3 phases, first_indices={-6,-5,-4}, W=13 taps.
// out[c, n] = sum_j x[c, (n%3 - 6) + 2*(n/3) + j] * w[n%3][j], zero-padded x.
//
// Warp-halo scheme, T=8 tile: thread t owns input floats [16t, 16t+16) via
// four coalesced LDG.128 (front-batched, MLP_p1=4); 6/7-float halos from
// lanes l+-1 via SHFL after the loads; edge lanes patch after the shuffle
// chain (R8: divergence before shuffles regresses). Weights in __constant__.
// Streaming hints on touch-once streams. 24 outputs/thread. No early return
// (250k threads/ch not warp-divisible); store-time guard instead.

#define C_CH    8
#define NPHASE  3
#define WTAPS   13
#define OUT_PT  24   // outputs per thread (8 units x 3 phases)
#define BLK     256

__constant__ float cw[NPHASE * WTAPS];

__global__ __launch_bounds__(BLK, 5) void resample_16_24_kernel(
    const float* __restrict__ x, float* __restrict__ out, int L, int tot)
{
    const int c = blockIdx.y;
    const int t = blockIdx.x * BLK + threadIdx.x;
    const int n0 = t * OUT_PT;
    const int lane = threadIdx.x & 31;

    const float* xc = x + (size_t)c * (size_t)L;
    const int g0 = 16 * t;          // own floats [g0, g0+16)
    const float4* p = reinterpret_cast<const float4*>(xc + g0);

    // Own data: 4 coalesced vector loads, streaming hint. Out-of-range
    // threads (tail warps) take the guarded scalar path and read zeros.
    float4 A, B, C, D;
    if (g0 + 16 <= L) {
        A = __ldcs(&p[0]); B = __ldcs(&p[1]);
        C = __ldcs(&p[2]); D = __ldcs(&p[3]);
    } else {
        float a[16];
#pragma unroll
        for (int q = 0; q < 16; q++) {
            int g = g0 + q;
            a[q] = (g < L) ? xc[g] : 0.0f;
        }
        A = make_float4(a[0],  a[1],  a[2],  a[3]);
        B = make_float4(a[4],  a[5],  a[6],  a[7]);
        C = make_float4(a[8],  a[9],  a[10], a[11]);
        D = make_float4(a[12], a[13], a[14], a[15]);
    }

    // xin[k] = x[16t - 8 + k]; taps use xin[2..30].
    float xin[31];
    const unsigned m = 0xffffffffu;
    // left halo (from lane-1's C.z..D.w)
    xin[2] = __shfl_up_sync(m, C.z, 1);
    xin[3] = __shfl_up_sync(m, C.w, 1);
    xin[4] = __shfl_up_sync(m, D.x, 1);
    xin[5] = __shfl_up_sync(m, D.y, 1);
    xin[6] = __shfl_up_sync(m, D.z, 1);
    xin[7] = __shfl_up_sync(m, D.w, 1);
    // own
    xin[8]  = A.x; xin[9]  = A.y; xin[10] = A.z; xin[11] = A.w;
    xin[12] = B.x; xin[13] = B.y; xin[14] = B.z; xin[15] = B.w;
    xin[16] = C.x; xin[17] = C.y; xin[18] = C.z; xin[19] = C.w;
    xin[20] = D.x; xin[21] = D.y; xin[22] = D.z; xin[23] = D.w;
    // right halo (from lane+1's A.x..B.z)
    xin[24] = __shfl_down_sync(m, A.x, 1);
    xin[25] = __shfl_down_sync(m, A.y, 1);
    xin[26] = __shfl_down_sync(m, A.z, 1);
    xin[27] = __shfl_down_sync(m, A.w, 1);
    xin[28] = __shfl_down_sync(m, B.x, 1);
    xin[29] = __shfl_down_sync(m, B.y, 1);
    xin[30] = __shfl_down_sync(m, B.z, 1);

    // Warp-edge patches (after the shuffle chain).
    if (lane == 0) {
        if (g0 - 8 >= 0) {
            float4 P2 = __ldg(&p[-2]);   // k = 0..3
            float4 P1 = __ldg(&p[-1]);   // k = 4..7
            xin[2] = P2.z; xin[3] = P2.w;
            xin[4] = P1.x; xin[5] = P1.y; xin[6] = P1.z; xin[7] = P1.w;
        } else {
#pragma unroll
            for (int k = 2; k < 8; k++) {
                int g = g0 - 8 + k;
                xin[k] = (g >= 0 && g < L) ? xc[g] : 0.0f;
            }
        }
    }
    if (lane == 31) {
        if (g0 + 24 <= L) {
            float4 N0 = __ldg(&p[4]);    // k = 24..27
            float4 N1 = __ldg(&p[5]);    // k = 28..31
            xin[24] = N0.x; xin[25] = N0.y; xin[26] = N0.z; xin[27] = N0.w;
            xin[28] = N1.x; xin[29] = N1.y; xin[30] = N1.z;
        } else {
#pragma unroll
            for (int k = 24; k < 31; k++) {
                int g = g0 - 8 + k;
                xin[k] = (g >= 0 && g < L) ? xc[g] : 0.0f;
            }
        }
    }

    // 24 outputs: n = n0 + 3u + i reads xin[(2+i+2u) .. +12]; weights from
    // constant bank. Quad-by-quad with immediate streaming store.
    if (n0 < tot) {                  // tot divisible by 24 -> full tiles only
        float* oc = out + (size_t)c * (size_t)tot + n0;
        float4* po = reinterpret_cast<float4*>(oc);
#pragma unroll
        for (int q = 0; q < 6; q++) {
            float o4[4];
#pragma unroll
            for (int r = 0; r < 4; r++) {
                const int n = 4 * q + r;
                const int u = n / 3;
                const int i = n % 3;
                const int base = 2 + i + 2 * u;
                float s = 0.0f;
#pragma unroll
                for (int j = 0; j < WTAPS; j++)
                    s = fmaf(xin[base + j], cw[i * WTAPS + j], s);
                o4[r] = s;
            }
            __stcs(&po[q], make_float4(o4[0], o4[1], o4[2], o4[3]));
        }
    }
}

extern "C" void kernel_launch(void* const* d_in, const int* in_sizes, int n_in,
                              void* d_out, int out_size)
{
    const float* x   = (const float*)d_in[0];
    const float* wgt = (const float*)d_in[1];
    float* out = (float*)d_out;

    const int L   = in_sizes[0] / C_CH;   // 4,000,000
    const int tot = out_size   / C_CH;    // 6,000,000 (divisible by 24)

    // Stage filter bank into constant memory (DtoD, on captured legacy stream)
    cudaMemcpyToSymbolAsync(cw, wgt, NPHASE * WTAPS * sizeof(float), 0,
                            cudaMemcpyDeviceToDevice, 0);

    const int threads_per_ch = (tot + OUT_PT - 1) / OUT_PT;   // 250,000
    const int bx = (threads_per_ch + BLK - 1) / BLK;          // 977
    dim3 grid(bx, C_CH);
    resample_16_24_kernel<<<grid, BLK>>>(x, out, L, tot);
}

// round 11
// speedup vs baseline: 1.1578x; 1.1578x over previous
#include <cuda_runtime.h>

// 16k -> 24k polyphase resampler (torchaudio/kaldi defaults).
// in_unit=2, out_unit=3 phases, first_indices={-6,-5,-4}, W=13 taps.
// out[c, n] = sum_j x[c, (n%3 - 6) + 2*(n/3) + j] * w[n%3][j], zero-padded x.
//
// R9 warp-halo structure (T=4 tile: own floats [8t,8t+8) via 2 coalesced
// LDG.128, halos via SHFL, edge patch after the shuffle chain, constant-bank
// weights, streaming hints). NEW: each thread processes TWO far-apart tiles
// (t and t+250000) with all 4 global loads front-batched, so tile 2's loads
// are in flight under tile 1's shuffle+compute (2x memory parallelism at
// unchanged per-tile serial cost). 250000 % 32 == 0 -> warps never straddle
// channels in either group; halo shuffles stay valid.

#define C_CH    8
#define NPHASE  3
#define WTAPS   13
#define OUT_PT  12          // outputs per tile (4 units x 3 phases)
#define BLK     256
#define HALF    250000      // tiles per channel-half (500000 total per ch)

__constant__ float cw[NPHASE * WTAPS];

// Shuffle-halo + compute + store for one T=4 tile. A/B already loaded.
__device__ __forceinline__ void tile_pass(
    float4 A, float4 B, int t, int lane,
    const float* __restrict__ xc, float* __restrict__ out_c,
    int L, int tot)
{
    const int g0 = 8 * t;
    const float4* p = reinterpret_cast<const float4*>(xc + g0);

    // xin[k] = x[8t - 8 + k]; taps use xin[2..22].
    float xin[23];
    const unsigned m = 0xffffffffu;
    xin[2]  = __shfl_up_sync(m, A.z, 1);
    xin[3]  = __shfl_up_sync(m, A.w, 1);
    xin[4]  = __shfl_up_sync(m, B.x, 1);
    xin[5]  = __shfl_up_sync(m, B.y, 1);
    xin[6]  = __shfl_up_sync(m, B.z, 1);
    xin[7]  = __shfl_up_sync(m, B.w, 1);
    xin[8]  = A.x; xin[9]  = A.y; xin[10] = A.z; xin[11] = A.w;
    xin[12] = B.x; xin[13] = B.y; xin[14] = B.z; xin[15] = B.w;
    xin[16] = __shfl_down_sync(m, A.x, 1);
    xin[17] = __shfl_down_sync(m, A.y, 1);
    xin[18] = __shfl_down_sync(m, A.z, 1);
    xin[19] = __shfl_down_sync(m, A.w, 1);
    xin[20] = __shfl_down_sync(m, B.x, 1);
    xin[21] = __shfl_down_sync(m, B.y, 1);
    xin[22] = __shfl_down_sync(m, B.z, 1);

    // Warp-edge halo patch (after the shuffle chain).
    if (lane == 0) {
        const int gl = g0 - 8;
        if (gl >= 0) {
            float4 PA = __ldg(&p[-2]);
            float4 PB = __ldg(&p[-1]);
            xin[2] = PA.z; xin[3] = PA.w;
            xin[4] = PB.x; xin[5] = PB.y; xin[6] = PB.z; xin[7] = PB.w;
        } else {
#pragma unroll
            for (int q = 2; q < 8; q++) {
                int g = gl + q;
                xin[q] = (g >= 0 && g < L) ? xc[g] : 0.0f;
            }
        }
    }
    if (lane == 31) {
        const int gr = g0 + 8;
        if (gr + 8 <= L) {
            float4 NA = __ldg(&p[2]);
            float4 NB = __ldg(&p[3]);
            xin[16] = NA.x; xin[17] = NA.y; xin[18] = NA.z; xin[19] = NA.w;
            xin[20] = NB.x; xin[21] = NB.y; xin[22] = NB.z;
        } else {
#pragma unroll
            for (int q = 0; q < 7; q++) {
                int g = gr + q;
                xin[16 + q] = (g >= 0 && g < L) ? xc[g] : 0.0f;
            }
        }
    }

    const int n0 = t * OUT_PT;
    if (n0 >= tot) return;
    float4* po = reinterpret_cast<float4*>(out_c + n0);
#pragma unroll
    for (int q = 0; q < 3; q++) {
        float o4[4];
#pragma unroll
        for (int r = 0; r < 4; r++) {
            const int n = 4 * q + r;
            const int u = n / 3;
            const int i = n % 3;
            const int base = 2 + i + 2 * u;
            float s = 0.0f;
#pragma unroll
            for (int j = 0; j < WTAPS; j++)
                s = fmaf(xin[base + j], cw[i * WTAPS + j], s);
            o4[r] = s;
        }
        __stcs(&po[q], make_float4(o4[0], o4[1], o4[2], o4[3]));
    }
}

__global__ __launch_bounds__(BLK, 5) void resample_16_24_kernel(
    const float* __restrict__ x, float* __restrict__ out, int L, int tot)
{
    const int c = blockIdx.y;
    const int lane = threadIdx.x & 31;
    const int t1 = blockIdx.x * BLK + threadIdx.x;   // tile in first half
    const int t2 = t1 + HALF;                        // tile in second half

    const float* xc = x + (size_t)c * (size_t)L;
    float* out_c = out + (size_t)c * (size_t)tot;

    // Front-batch all 4 global loads (2 tiles). Guarded tails read zeros so
    // every lane still participates in the shuffle chains.
    const int g1 = 8 * t1;
    const int g2 = 8 * t2;
    float4 A1, B1, A2, B2;
    if (g1 + 8 <= L) {
        const float4* p1 = reinterpret_cast<const float4*>(xc + g1);
        A1 = __ldcs(&p1[0]); B1 = __ldcs(&p1[1]);
    } else {
        A1 = make_float4(0.f, 0.f, 0.f, 0.f);
        B1 = make_float4(0.f, 0.f, 0.f, 0.f);
    }
    if (g2 + 8 <= L) {
        const float4* p2 = reinterpret_cast<const float4*>(xc + g2);
        A2 = __ldcs(&p2[0]); B2 = __ldcs(&p2[1]);
    } else {
        A2 = make_float4(0.f, 0.f, 0.f, 0.f);
        B2 = make_float4(0.f, 0.f, 0.f, 0.f);
    }

    // Tile 2's loads remain in flight during tile 1's shuffle/compute.
    tile_pass(A1, B1, t1, lane, xc, out_c, L, tot);
    tile_pass(A2, B2, t2, lane, xc, out_c, L, tot);
}

extern "C" void kernel_launch(void* const* d_in, const int* in_sizes, int n_in,
                              void* d_out, int out_size)
{
    const float* x   = (const float*)d_in[0];
    const float* wgt = (const float*)d_in[1];
    float* out = (float*)d_out;

    const int L   = in_sizes[0] / C_CH;   // 4,000,000
    const int tot = out_size   / C_CH;    // 6,000,000 (divisible by 12)

    // Stage filter bank into constant memory (DtoD, on captured legacy stream)
    cudaMemcpyToSymbolAsync(cw, wgt, NPHASE * WTAPS * sizeof(float), 0,
                            cudaMemcpyDeviceToDevice, 0);

    const int bx = (HALF + BLK - 1) / BLK;   // 977 blocks covers 250,112 >= HALF
    dim3 grid(bx, C_CH);
    resample_16_24_kernel<<<grid, BLK>>>(x, out, L, tot);
}